// round 17
// baseline (speedup 1.0000x reference)
#include <cuda_runtime.h>
#include <cstdint>
#include <cstddef>

#define TL 512
#define NB 2048
#define NB16 (NB*16)
#define FULL 0xffffffffu

// scratch: hproj_seq, T*B*16 floats = 64 MiB
__device__ float g_hproj[(size_t)TL * NB * 16];

__device__ __forceinline__ float sigf(float x){
  return __fdividef(1.f, 1.f + __expf(-x));
}
__device__ __forceinline__ float tanh_fast(float x){
  return __fdividef(2.f, 1.f + __expf(-2.f * x)) - 1.f;
}

// ---- packed f32x2 helpers ----
__device__ __forceinline__ uint64_t pk2(float lo, float hi){
  uint64_t r; asm("mov.b64 %0, {%1, %2};" : "=l"(r) : "f"(lo), "f"(hi)); return r;
}
__device__ __forceinline__ uint64_t fma2(uint64_t a, uint64_t b, uint64_t c){
  uint64_t d; asm("fma.rn.f32x2 %0, %1, %2, %3;" : "=l"(d) : "l"(a), "l"(b), "l"(c));
  return d;
}
__device__ __forceinline__ float dot16p(const uint64_t w[8], const uint64_t v[8]){
  const uint64_t z = 0;
  uint64_t a0 = fma2(w[0], v[0], z);
  uint64_t a1 = fma2(w[1], v[1], z);
  a0 = fma2(w[2], v[2], a0);
  a1 = fma2(w[3], v[3], a1);
  a0 = fma2(w[4], v[4], a0);
  a1 = fma2(w[5], v[5], a1);
  a0 = fma2(w[6], v[6], a0);
  a1 = fma2(w[7], v[7], a1);
  uint64_t s; asm("add.rn.f32x2 %0, %1, %2;" : "=l"(s) : "l"(a0), "l"(a1));
  float lo, hi; asm("mov.b64 {%0, %1}, %2;" : "=f"(lo), "=f"(hi) : "l"(s));
  return lo + hi;
}
__device__ __forceinline__ void ldv8p(const float* p, uint64_t v[8]){
  #pragma unroll
  for (int i = 0; i < 4; i++){
    ulonglong2 q = reinterpret_cast<const ulonglong2*>(p)[i];
    v[2*i] = q.x; v[2*i+1] = q.y;
  }
}

// ============================================================================
// Phase 1: backward LSTM scan + fused hproj. Double-buffered hbuf:
// WAR syncwarp removed — 1 sync per step instead of 2.
// ============================================================================
__global__ __launch_bounds__(64)
void lstm_bwd_kernel(const float* __restrict__ x,
                     const float* __restrict__ Wih,
                     const float* __restrict__ Whh,
                     const float* __restrict__ bih,
                     const float* __restrict__ bhh,
                     const float* __restrict__ cW1,
                     const float* __restrict__ cb1)
{
  const int l = threadIdx.x & 31;
  const int w = threadIdx.x >> 5;
  const int b = blockIdx.x * 2 + w;
  const int lo = l & 15;

  __shared__ __align__(16) float sH[2][2][16];   // [warp][slot][elem]

  const int r0 = l, r1 = l + 32;
  uint64_t w0[8], w1[8], wHp[8];
  #pragma unroll
  for (int j = 0; j < 8; j++){
    w0[j]  = pk2(Whh[r0*16 + 2*j], Whh[r0*16 + 2*j + 1]);
    w1[j]  = pk2(Whh[r1*16 + 2*j], Whh[r1*16 + 2*j + 1]);
    wHp[j] = pk2(cW1[lo*32 + 2*j], cW1[lo*32 + 2*j + 1]);
  }
  const float wx0 = Wih[r0], wx1 = Wih[r1];
  const float b0 = bih[r0] + bhh[r0];
  const float b1 = bih[r1] + bhh[r1];
  const float bHp = cb1[lo];

  if (l < 16) sH[w][0][l] = 0.f;
  int cur = 0;
  float c = 0.f;
  __syncwarp();

  const float* xb = x + b;
  float* hpout = g_hproj + (size_t)b * 16 + lo;

  float xt = __ldg(xb + (size_t)(TL-1) * NB);

  for (int t = TL - 1; t >= 0; --t){
    float xn = 0.f;
    if (t > 0) xn = __ldg(xb + (size_t)(t-1) * NB);

    uint64_t hv[8]; ldv8p(sH[w][cur], hv);

    float hp = bHp + dot16p(wHp, hv);
    if (l < 16 && t != TL - 1)
      hpout[(size_t)(t+1) * NB16] = hp;

    float a0 = fmaf(xt, wx0, b0) + dot16p(w0, hv);
    float a1 = fmaf(xt, wx1, b1) + dot16p(w1, hv);

    float p, q = 0.f;
    if (l < 16) { p = sigf(a0) * tanh_fast(a1); }
    else        { p = sigf(a0); q = sigf(a1); }
    float pf = __shfl_xor_sync(FULL, p, 16);
    float qo = __shfl_xor_sync(FULL, q, 16);
    if (l < 16){
      c = fmaf(pf, c, p);
      float hn = qo * tanh_fast(c);
      sH[w][cur ^ 1][l] = hn;      // write OTHER slot: no WAR with this step's reads
    }
    cur ^= 1;
    __syncwarp();                  // RAW: make write visible for next step's reads
    xt = xn;
  }

  {
    uint64_t hv[8]; ldv8p(sH[w][cur], hv);
    float hp = bHp + dot16p(wHp, hv);
    if (l < 16) hpout[0] = hp;
  }
}

// ============================================================================
// Phase 2: FUSED DKF + decoder + transition.
// dec1 smem weights now read as packed u64 pairs -> dot16p (8 FFMA2),
// replacing 16 scalar FFMA + unpk16. tr2 in registers (R15).
// ============================================================================
__global__ __launch_bounds__(64, 7)
void dkf_fused_kernel(const float* __restrict__ eps,
                      const float* __restrict__ cW1,
                      const float* __restrict__ cW2, const float* __restrict__ cb2,
                      const float* __restrict__ eW1, const float* __restrict__ eb1,
                      const float* __restrict__ eW2, const float* __restrict__ eb2,
                      const float* __restrict__ dW1, const float* __restrict__ db1,
                      const float* __restrict__ dW2, const float* __restrict__ db2,
                      const float* __restrict__ tW1, const float* __restrict__ tb1,
                      const float* __restrict__ tW2, const float* __restrict__ tb2,
                      float* __restrict__ out)
{
  const int l = threadIdx.x & 31;
  const int w = threadIdx.x >> 5;
  const int b = blockIdx.x * 2 + w;
  const int lo = l & 15;
  const bool low = (l < 16);

  __shared__ __align__(16) float sm[2][80];
  __shared__ __align__(16) float4 d1q[16*5];    // dec1 rows, stride 5 (conflict-free)
  float* SA = &sm[w][0];    // a1 (16)
  float* ST = &sm[w][16];   // t1 (16)
  float* SD = &sm[w][32];   // d1 (16)
  float* SC = &sm[w][48];   // e1 (16)
  float* SZ = &sm[w][64];   // z  (16)

  // ---- cooperative smem weight fill (block-wide) ----
  {
    const float4* d4 = reinterpret_cast<const float4*>(dW1);   // 64 float4
    if (threadIdx.x < 64){
      int idx = threadIdx.x;
      d1q[(idx >> 2) * 5 + (idx & 3)] = d4[idx];
    }
  }

  // ---- per-lane register weight rows ----
  // w1r: low = cW1 z-cols row lo ; high = tW1 row lo
  uint64_t w1r[8];
  #pragma unroll
  for (int j = 0; j < 8; j++){
    const float* src = low ? (cW1 + lo*32 + 16) : (tW1 + lo*16);
    w1r[j] = pk2(src[2*j], src[2*j+1]);
  }
  // w3r: tr2 row l (all lanes)
  uint64_t w3r[8];
  #pragma unroll
  for (int j = 0; j < 8; j++)
    w3r[j] = pk2(tW2[l*16 + 2*j], tW2[l*16 + 2*j + 1]);
  // w4r: low = fused M row lo (eW1@cW2); high = dW2 row (l&1)
  uint64_t w4r[8];
  float bM = 0.f;
  if (low){
    float e1w[8];
    #pragma unroll
    for (int k = 0; k < 8; k++) e1w[k] = eW1[lo*8 + k];
    #pragma unroll
    for (int cc = 0; cc < 8; cc++){
      float ax = 0.f, ay = 0.f;
      #pragma unroll
      for (int k = 0; k < 8; k++){
        ax = fmaf(e1w[k], cW2[k*16 + 2*cc],     ax);
        ay = fmaf(e1w[k], cW2[k*16 + 2*cc + 1], ay);
      }
      w4r[cc] = pk2(ax, ay);
    }
    bM = eb1[lo];
    #pragma unroll
    for (int k = 0; k < 8; k++) bM = fmaf(e1w[k], cb2[k], bM);
  } else {
    #pragma unroll
    for (int j = 0; j < 8; j++)
      w4r[j] = pk2(dW2[(l&1)*16 + 2*j], dW2[(l&1)*16 + 2*j + 1]);
  }
  // wDr: enc2 row l
  uint64_t wDr[8];
  #pragma unroll
  for (int j = 0; j < 8; j++)
    wDr[j] = pk2(eW2[l*16 + 2*j], eW2[l*16 + 2*j + 1]);

  const float bT1r = tb1[lo];
  const float bD1r = db1[lo];
  const float bT2r = tb2[l];
  const float bD2r = db2[l & 1];
  const float bDr  = eb2[l];

  if (low) SZ[lo] = 0.f;      // z0
  __syncthreads();            // weights + SZ visible block-wide

  const float* hpp = g_hproj + (size_t)b * 16 + lo;
  const float* epp = eps     + (size_t)b * 16 + lo;
  float*       outp = out    + (size_t)b * 66;

  // ---- 4-deep prefetch ring ----
  float hp0 = __ldg(hpp);
  float hp1 = __ldg(hpp + (size_t)1 * NB16);
  float hp2 = __ldg(hpp + (size_t)2 * NB16);
  float hp3 = __ldg(hpp + (size_t)3 * NB16);
  float ep0 = __ldg(epp);
  float ep1 = __ldg(epp + (size_t)1 * NB16);
  float ep2 = __ldg(epp + (size_t)2 * NB16);
  float ep3 = __ldg(epp + (size_t)3 * NB16);

  const ulonglong2* dqp = reinterpret_cast<const ulonglong2*>(&d1q[lo*5]);

  #define DKF_STEP(T, HPV, EPSV)                                          \
  {                                                                       \
    /* stage 2: A|tr1 (chain) + dec1 (packed smem weights, off-chain) */  \
    uint64_t zv[8]; ldv8p(SZ, zv);                                        \
    float base1 = low ? (HPV) : bT1r;                                     \
    float v1 = tanh_fast(base1 + dot16p(w1r, zv));   /* a1 | t1 */        \
    uint64_t dqw[8];                                                      \
    _Pragma("unroll")                                                     \
    for (int i = 0; i < 4; i++){                                          \
      ulonglong2 q = dqp[i]; dqw[2*i] = q.x; dqw[2*i+1] = q.y;            \
    }                                                                     \
    float d1 = tanh_fast(bD1r + dot16p(dqw, zv));                         \
    if (low){ SA[lo] = v1; SD[lo] = d1; } else { ST[lo] = v1; }           \
    __syncwarp();                                                         \
    /* stage 4: tr2 (register weights) + (e1 | dec2) */                   \
    uint64_t tv[8]; ldv8p(ST, tv);                                        \
    outp[34 + l] = bT2r + dot16p(w3r, tv);                                \
    uint64_t av[8]; ldv8p(low ? SA : SD, av);                             \
    float base4 = low ? bM : bD2r;                                        \
    float v4 = base4 + dot16p(w4r, av);              /* e1pre | dx */     \
    if (low) SC[lo] = tanh_fast(v4);                                      \
    else if (((unsigned)(l - 16)) < 2u && (T) > 0)                        \
      (outp - (size_t)NB * 66)[l - 16] = v4;         /* mu_x/logvar_x */  \
    __syncwarp();                                                         \
    /* stage 6: enc2 + sample */                                          \
    uint64_t ev[8]; ldv8p(SC, ev);                                        \
    float e2 = bDr + dot16p(wDr, ev);                                     \
    outp[2 + l] = e2;                                                     \
    float lvz = __shfl_xor_sync(FULL, e2, 16);                            \
    float znew = fmaf((EPSV), __expf(0.5f * lvz), e2);                    \
    if (low) SZ[lo] = znew;                                               \
    __syncwarp();                                                         \
    outp += (size_t)NB * 66;                                              \
  }

  #pragma unroll 1
  for (int t = 0; t < TL; t += 4){
    int t4 = t + 4; if (t4 > TL-1) t4 = TL-1;
    int t5 = t + 5; if (t5 > TL-1) t5 = TL-1;
    int t6 = t + 6; if (t6 > TL-1) t6 = TL-1;
    int t7 = t + 7; if (t7 > TL-1) t7 = TL-1;

    float hpa = __ldg(hpp + (size_t)t4 * NB16);
    float epa = __ldg(epp + (size_t)t4 * NB16);
    DKF_STEP(t + 0, hp0, ep0);
    hp0 = hpa; ep0 = epa;

    float hpb = __ldg(hpp + (size_t)t5 * NB16);
    float epb = __ldg(epp + (size_t)t5 * NB16);
    DKF_STEP(t + 1, hp1, ep1);
    hp1 = hpb; ep1 = epb;

    float hpc = __ldg(hpp + (size_t)t6 * NB16);
    float epc = __ldg(epp + (size_t)t6 * NB16);
    DKF_STEP(t + 2, hp2, ep2);
    hp2 = hpc; ep2 = epc;

    float hpd = __ldg(hpp + (size_t)t7 * NB16);
    float epd = __ldg(epp + (size_t)t7 * NB16);
    DKF_STEP(t + 3, hp3, ep3);
    hp3 = hpd; ep3 = epd;
  }
  #undef DKF_STEP

  // epilogue: decoder for z_{TL-1} (outp now = base + TL*NB*66)
  {
    uint64_t zv[8]; ldv8p(SZ, zv);
    uint64_t dqw[8];
    #pragma unroll
    for (int i = 0; i < 4; i++){
      ulonglong2 q = dqp[i]; dqw[2*i] = q.x; dqw[2*i+1] = q.y;
    }
    float d1 = tanh_fast(bD1r + dot16p(dqw, zv));
    if (low) SD[lo] = d1;
    __syncwarp();
    uint64_t dv[8]; ldv8p(SD, dv);
    float dx = bD2r + dot16p(w4r, dv);     // valid on high lanes
    if (((unsigned)(l - 16)) < 2u)
      (outp - (size_t)NB * 66)[l - 16] = dx;
  }
}

extern "C" void kernel_launch(void* const* d_in, const int* in_sizes, int n_in,
                              void* d_out, int out_size)
{
  const float* x   = (const float*)d_in[0];
  const float* eps = (const float*)d_in[1];
  const float* Wih = (const float*)d_in[2];
  const float* Whh = (const float*)d_in[3];
  const float* bih = (const float*)d_in[4];
  const float* bhh = (const float*)d_in[5];
  const float* cW1 = (const float*)d_in[6];
  const float* cb1 = (const float*)d_in[7];
  const float* cW2 = (const float*)d_in[8];
  const float* cb2 = (const float*)d_in[9];
  const float* eW1 = (const float*)d_in[10];
  const float* eb1 = (const float*)d_in[11];
  const float* eW2 = (const float*)d_in[12];
  const float* eb2 = (const float*)d_in[13];
  const float* dW1 = (const float*)d_in[14];
  const float* db1 = (const float*)d_in[15];
  const float* dW2 = (const float*)d_in[16];
  const float* db2 = (const float*)d_in[17];
  const float* tW1 = (const float*)d_in[18];
  const float* tb1 = (const float*)d_in[19];
  const float* tW2 = (const float*)d_in[20];
  const float* tb2 = (const float*)d_in[21];
  float* out = (float*)d_out;

  lstm_bwd_kernel<<<NB/2, 64>>>(x, Wih, Whh, bih, bhh, cW1, cb1);
  dkf_fused_kernel<<<NB/2, 64>>>(eps, cW1, cW2, cb2, eW1, eb1, eW2, eb2,
                                 dW1, db1, dW2, db2, tW1, tb1, tW2, tb2, out);
}